// round 11
// baseline (speedup 1.0000x reference)
#include <cuda_runtime.h>
#include <math.h>
#include <stdint.h>

#define NROW 4096
#define CH   1024
#define MQ   8
#define KQ   2048
#define DQ   128
#define CAP  64       // scoring-side list cap
#define CAPG 32       // global per-row candidate cap (speculative, E[cnt]~10)
#define UTHR0 0.995f  // fixed speculative threshold; P(umax<UTHR0)=3.6e-5

// Static scratch (all rewritten deterministically every replay; cm2 atomicMax
// is idempotent over the fixed input set).
static __device__ unsigned g_cm2[2][MQ];
static __device__ int      g_k0[NROW * MQ];
static __device__ float    g_umax[2][NROW * MQ];
static __device__ int      g_cap[2][NROW * MQ];            // raw counts (may exceed CAPG)
static __device__ uint2    g_cand[2][NROW * MQ][CAPG];     // (u bits, k)

// One warp per 8 consecutive k: 8 interleaved butterflies (MLP 8), one atomicMax.
__global__ void cm2_k(const float* __restrict__ cb0, const float* __restrict__ cb1) {
    const int level = blockIdx.y;
    const float* cb = level ? cb1 : cb0;
    const int w    = (blockIdx.x * blockDim.x + threadIdx.x) >> 5;
    const int lane = threadIdx.x & 31;
    if (w >= (MQ * KQ) / 8) return;
    float s[8];
#pragma unroll
    for (int r = 0; r < 8; r++) {
        float4 v = reinterpret_cast<const float4*>(cb)[(size_t)(w * 8 + r) * (DQ / 4) + lane];
        s[r] = v.x * v.x + v.y * v.y + v.z * v.z + v.w * v.w;
    }
#pragma unroll
    for (int o = 16; o; o >>= 1)
#pragma unroll
        for (int r = 0; r < 8; r++) s[r] += __shfl_xor_sync(0xffffffffu, s[r], o);
    if (lane == 0) {
        float mx = s[0];
#pragma unroll
        for (int r = 1; r < 8; r++) mx = fmaxf(mx, s[r]);
        atomicMax(&g_cm2[level][(w * 8) >> 11], __float_as_uint(mx));
    }
}

__device__ __forceinline__ float warp_sum(float v) {
#pragma unroll
    for (int o = 16; o; o >>= 1) v += __shfl_xor_sync(0xffffffffu, v, o);
    return v;
}
__device__ __forceinline__ float warp_max_pos(float v) {   // non-negative floats
    unsigned r;
    asm("redux.sync.max.u32 %0, %1, 0xffffffff;" : "=r"(r) : "r"(__float_as_uint(v)));
    return __uint_as_float(r);
}

__constant__ float c_SCALE = 45.25483399593904f;   // sqrt(2048)

// Threshold: g(u) = -log(-log u) monotone in u; candidate iff u >= uthr.
// delta = Cauchy-Schwarz logit-spread bound, inflated for fp noise.
__device__ __forceinline__ float make_uthr(float umax, float t, float x2, float cm2) {
    const float EPSF = 1e-6f, HI = (float)(1.0 - 1e-6);
    const float cmax = sqrtf(cm2);
    float delta = (t / c_SCALE) * (4.0f * sqrtf(x2) * cmax + cm2);
    delta = delta * 1.01f + 0.02f;
    float ucm  = fminf(fmaxf(umax, EPSF), HI);
    float gm   = -logf(-logf(ucm));
    float uthr = expf(-expf(-(gm - delta))) * (1.0f - 1e-5f);
    return fminf(uthr, umax);                 // max element always qualifies
}

// ---- K1: pure streaming. One warp per (row, level): burst, max, speculative
// push vs fixed UTHR0, write list+count+umax. No codebooks, no logs, tiny tail.
__global__ void __launch_bounds__(256) stream_k(
    const float* __restrict__ u0, const float* __restrict__ u1)
{
    __shared__ int   s_cnt[8];
    __shared__ int   s_k[8][CAPG];
    __shared__ float s_u[8][CAPG];
    const int w    = threadIdx.x >> 5;
    const int lane = threadIdx.x & 31;
    const int row  = blockIdx.x * 8 + w;
    const int lvl  = blockIdx.y;
    const float4* urow = reinterpret_cast<const float4*>(lvl ? u1 : u0)
                         + (size_t)row * (KQ / 4);

    // Front-batched burst: load + fmax ONLY.
    float4 ur[16];
    float umax = 0.0f;
#pragma unroll
    for (int j = 0; j < 16; j++) {
        ur[j] = urow[j * 32 + lane];
        umax = fmaxf(umax, fmaxf(fmaxf(ur[j].x, ur[j].y), fmaxf(ur[j].z, ur[j].w)));
    }
    if (lane == 0) s_cnt[w] = 0;
    umax = warp_max_pos(umax);

    // Branch-free mask vs fixed threshold; one ballot; rare pushes.
    unsigned m0 = 0u, m1 = 0u;
#pragma unroll
    for (int j = 0; j < 16; j++) {
        const float4 v = ur[j];
        unsigned b = (unsigned)(v.x >= UTHR0) | ((unsigned)(v.y >= UTHR0) << 1)
                   | ((unsigned)(v.z >= UTHR0) << 2) | ((unsigned)(v.w >= UTHR0) << 3);
        if (j < 8) m0 |= b << (4 * j); else m1 |= b << (4 * (j - 8));
    }
    __syncwarp();
    __ballot_sync(0xffffffffu, (m0 | m1) != 0u);
    if (m0 | m1) {
#pragma unroll
        for (int j = 0; j < 16; j++) {
            unsigned b = (j < 8) ? (m0 >> (4 * j)) & 0xFu : (m1 >> (4 * (j - 8))) & 0xFu;
            if (b) {
                const int kb = (j * 32 + lane) * 4;
                const float4 v = ur[j];
                if (b & 1u) { int q = atomicAdd(&s_cnt[w], 1); if (q < CAPG) { s_k[w][q] = kb + 0; s_u[w][q] = v.x; } }
                if (b & 2u) { int q = atomicAdd(&s_cnt[w], 1); if (q < CAPG) { s_k[w][q] = kb + 1; s_u[w][q] = v.y; } }
                if (b & 4u) { int q = atomicAdd(&s_cnt[w], 1); if (q < CAPG) { s_k[w][q] = kb + 2; s_u[w][q] = v.z; } }
                if (b & 8u) { int q = atomicAdd(&s_cnt[w], 1); if (q < CAPG) { s_k[w][q] = kb + 3; s_u[w][q] = v.w; } }
            }
        }
    }
    __syncwarp();
    const int cnt = s_cnt[w];
    if (lane == 0) { g_cap[lvl][row] = cnt; g_umax[lvl][row] = umax; }
    if (lane < cnt && lane < CAPG)
        g_cand[lvl][row][lane] = make_uint2(__float_as_uint(s_u[w][lane]), (unsigned)s_k[w][lane]);
}

// Score candidates: fast fp32 (|z-c|^2 single butterfly, 2-wide ILP) + rare
// fp64-faithful refinement on near-ties (margin 1e-2 >> combined fp noise).
__device__ __forceinline__ int score_pick(
    float4 z, float x2, float t, const float* __restrict__ cbm,
    int cnt, const int* kl, const float* ul, int lane)
{
    const float EPSF = 1e-6f, HI = (float)(1.0 - 1e-6);
    if (cnt <= 1) return kl[0];            // umax always qualifies -> cnt >= 1

    float best_s = -3.4e38f, sec_s = -3.4e38f;
    int   best_k = 0;
    for (int base = 0; base < cnt; base += 2) {
        float dd[2]; int kk[2];
#pragma unroll
        for (int i2 = 0; i2 < 2; i2++) {
            int i = base + i2; if (i > cnt - 1) i = cnt - 1;
            int k = kl[i]; kk[i2] = k;
            float4 c = reinterpret_cast<const float4*>(cbm)[(size_t)k * (DQ / 4) + lane];
            float ex = z.x - c.x, ey = z.y - c.y, ez = z.z - c.z, ew = z.w - c.w;
            dd[i2] = ex * ex + ey * ey + ez * ez + ew * ew;
        }
#pragma unroll
        for (int o = 16; o; o >>= 1) {
            dd[0] += __shfl_xor_sync(0xffffffffu, dd[0], o);
            dd[1] += __shfl_xor_sync(0xffffffffu, dd[1], o);
        }
#pragma unroll
        for (int i2 = 0; i2 < 2; i2++) {
            int i = base + i2; if (i >= cnt) break;
            float uc = fminf(fmaxf(ul[i], EPSF), HI);
            float g  = -logf(-logf(uc));
            float sc = -dd[i2] / c_SCALE * t + g;
            int   k  = kk[i2];
            if (sc > best_s || (sc == best_s && k < best_k)) {
                sec_s = best_s; best_s = sc; best_k = k;
            } else if (sc > sec_s) sec_s = sc;
        }
    }

    if (best_s - sec_s < 1e-2f) {          // rare: reference-faithful rescore
        best_s = -3.4e38f; best_k = 0;
        for (int i = 0; i < cnt; i++) {
            const int k = kl[i];
            float4 c = reinterpret_cast<const float4*>(cbm)[(size_t)k * (DQ / 4) + lane];
            float p = warp_sum(z.x * c.x + z.y * c.y + z.z * c.z + z.w * c.w);
            float q = warp_sum(c.x * c.x + c.y * c.y + c.z * c.z + c.w * c.w);
            double ucl = (double)fminf(fmaxf(ul[i], EPSF), HI);
            float  g   = (float)(-log(-log(ucl)));
            float dist  = __fadd_rn(__fadd_rn(x2, q), -__fmul_rn(2.0f, p));
            float logit = __fmul_rn(__fdiv_rn(-dist, c_SCALE), t);
            float sc    = __fadd_rn(logit, g);
            if (sc > best_s || (sc == best_s && k < best_k)) { best_s = sc; best_k = k; }
        }
    }
    __syncwarp();
    return best_k;
}

// Build final candidate list for a row: common path filters the speculative
// global list by the exact uthr; rare fallback re-streams the u row. The
// resulting set is exactly {k : u_k >= uthr} in both paths.
__device__ __forceinline__ int gather_cands(
    int lvl, int row, float uthr, const float* __restrict__ u,
    int lane, int* s_cnt, int* kl, float* ul)
{
    if (lane == 0) *s_cnt = 0;
    __syncwarp();
    const int cntraw = g_cap[lvl][row];
    if (uthr >= UTHR0 && cntraw <= CAPG) {
        if (lane < cntraw) {
            uint2 e = g_cand[lvl][row][lane];
            float uv = __uint_as_float(e.x);
            if (uv >= uthr) { int q = atomicAdd(s_cnt, 1); kl[q] = (int)e.y; ul[q] = uv; }
        }
    } else {
        // Rare (~3.6e-5 of rows): exact re-stream with the true threshold.
        const float4* urow = reinterpret_cast<const float4*>(u) + (size_t)row * (KQ / 4);
        for (int j = 0; j < 16; j++) {
            const float4 v = urow[j * 32 + lane];
            if (fmaxf(fmaxf(v.x, v.y), fmaxf(v.z, v.w)) >= uthr) {
                const int kb = (j * 32 + lane) * 4;
                if (v.x >= uthr) { int q = atomicAdd(s_cnt, 1); if (q < CAP) { kl[q] = kb + 0; ul[q] = v.x; } }
                if (v.y >= uthr) { int q = atomicAdd(s_cnt, 1); if (q < CAP) { kl[q] = kb + 1; ul[q] = v.y; } }
                if (v.z >= uthr) { int q = atomicAdd(s_cnt, 1); if (q < CAP) { kl[q] = kb + 2; ul[q] = v.z; } }
                if (v.w >= uthr) { int q = atomicAdd(s_cnt, 1); if (q < CAP) { kl[q] = kb + 3; ul[q] = v.w; } }
            }
        }
    }
    __syncwarp();
    int cnt = *s_cnt;
    return cnt > CAP ? CAP : cnt;
}

// ---- K2: level-0 scoring (no ur[16] anywhere -> low regs, high occ) ----
__global__ void __launch_bounds__(256) score0_k(
    const float* __restrict__ x, const float* __restrict__ cb0,
    const float* __restrict__ t0p, const float* __restrict__ u0)
{
    __shared__ int   s_cnt[8];
    __shared__ int   s_k[8][CAP];
    __shared__ float s_u[8][CAP];
    const int w    = threadIdx.x >> 5;
    const int lane = threadIdx.x & 31;
    const int row  = blockIdx.x * 8 + w;
    const int n    = row >> 3;
    const int m    = row & 7;

    float4 z = reinterpret_cast<const float4*>(x + (size_t)n * CH + m * DQ)[lane];
    float x2 = warp_sum(z.x * z.x + z.y * z.y + z.z * z.z + z.w * z.w);
    const float t0 = fmaxf(t0p[m], 1e-6f);
    float uthr = make_uthr(g_umax[0][row], t0, x2, __uint_as_float(g_cm2[0][m]));

    int cnt = gather_cands(0, row, uthr, u0, lane, &s_cnt[w], s_k[w], s_u[w]);
    const float* cbm0 = cb0 + (size_t)m * KQ * DQ;
    int k0 = score_pick(z, x2, t0, cbm0, cnt, s_k[w], s_u[w], lane);
    if (lane == 0) g_k0[row] = k0;
}

// ---- K3: level-1 scoring + output ----
__global__ void __launch_bounds__(256) score1_k(
    const float* __restrict__ x, const float* __restrict__ cb0,
    const float* __restrict__ cb1, const float* __restrict__ t1p,
    const float* __restrict__ u1, float* __restrict__ out)
{
    __shared__ int   s_cnt[8];
    __shared__ int   s_k[8][CAP];
    __shared__ float s_u[8][CAP];
    const int w    = threadIdx.x >> 5;
    const int lane = threadIdx.x & 31;
    const int row  = blockIdx.x * 8 + w;
    const int n    = row >> 3;
    const int m    = row & 7;

    float4 z = reinterpret_cast<const float4*>(x + (size_t)n * CH + m * DQ)[lane];
    const float* cbm0 = cb0 + (size_t)m * KQ * DQ;
    const float* cbm1 = cb1 + (size_t)m * KQ * DQ;
    const int k0 = g_k0[row];
    float4 c0 = reinterpret_cast<const float4*>(cbm0)[(size_t)k0 * (DQ / 4) + lane];
    float4 z1 = make_float4(z.x - c0.x, z.y - c0.y, z.z - c0.z, z.w - c0.w);
    float x2b = warp_sum(z1.x * z1.x + z1.y * z1.y + z1.z * z1.z + z1.w * z1.w);
    const float t1 = fmaxf(t1p[m], 1e-6f);
    float uthr = make_uthr(g_umax[1][row], t1, x2b, __uint_as_float(g_cm2[1][m]));

    int cnt = gather_cands(1, row, uthr, u1, lane, &s_cnt[w], s_k[w], s_u[w]);
    int k1 = score_pick(z1, x2b, t1, cbm1, cnt, s_k[w], s_u[w], lane);
    float4 c1 = reinterpret_cast<const float4*>(cbm1)[(size_t)k1 * (DQ / 4) + lane];

    float4 o = make_float4(c0.x + c1.x, c0.y + c1.y, c0.z + c1.z, c0.w + c1.w);
    reinterpret_cast<float4*>(out + (size_t)n * CH + m * DQ)[lane] = o;
}

extern "C" void kernel_launch(void* const* d_in, const int* in_sizes, int n_in,
                              void* d_out, int out_size) {
    const float *x = nullptr, *cb0 = nullptr, *cb1 = nullptr,
                *t0 = nullptr, *t1 = nullptr, *u0 = nullptr, *u1 = nullptr;
    for (int i = 0; i < n_in; i++) {
        const float* p = (const float*)d_in[i];
        const long sz = in_sizes[i];
        if      (sz == (long)NROW * CH)        { x = p; }
        else if (sz == (long)MQ * KQ * DQ)     { if (!cb0) cb0 = p; else cb1 = p; }
        else if (sz == (long)MQ)               { if (!t0)  t0  = p; else t1  = p; }
        else if (sz == (long)NROW * MQ * KQ)   { if (!u0)  u0  = p; else u1  = p; }
    }
    float* out = (float*)d_out;
    (void)out_size;

    dim3 gc((MQ * KQ) / (8 * 8), 2);             // 8 k's/warp, 8 warps/block
    cm2_k<<<gc, 256>>>(cb0, cb1);
    dim3 gs((NROW * MQ) / 8, 2);                 // one warp per (row, level)
    stream_k<<<gs, 256>>>(u0, u1);
    score0_k<<<(NROW * MQ) / 8, 256>>>(x, cb0, t0, u0);
    score1_k<<<(NROW * MQ) / 8, 256>>>(x, cb0, cb1, t1, u1, out);
}

// round 12
// speedup vs baseline: 1.0457x; 1.0457x over previous
#include <cuda_runtime.h>
#include <math.h>
#include <stdint.h>

#define NROW 4096
#define CH   1024
#define MQ   8
#define KQ   2048
#define DQ   128
#define CAP   64        // scoring-side list cap
#define CAPG  48        // global speculative cap (E[cnt]=23.6, P(>48)~3e-7)
#define UTHR0 0.9885f   // fixed speculative threshold, g0=4.457

// Static scratch (rewritten deterministically every replay; cm2 atomicMax is
// idempotent over the fixed input set).
static __device__ unsigned g_cm2[2][MQ];
static __device__ float    g_umax[2][NROW * MQ];
static __device__ int      g_cap[2][NROW * MQ];           // raw counts (can exceed CAPG)
static __device__ uint2    g_cand[2][NROW * MQ][CAPG];    // (u bits, k)

// One warp per 8 consecutive k: 8 interleaved butterflies, one atomicMax.
__global__ void cm2_k(const float* __restrict__ cb0, const float* __restrict__ cb1) {
    const int level = blockIdx.y;
    const float* cb = level ? cb1 : cb0;
    const int w    = (blockIdx.x * blockDim.x + threadIdx.x) >> 5;
    const int lane = threadIdx.x & 31;
    if (w >= (MQ * KQ) / 8) return;
    float s[8];
#pragma unroll
    for (int r = 0; r < 8; r++) {
        float4 v = reinterpret_cast<const float4*>(cb)[(size_t)(w * 8 + r) * (DQ / 4) + lane];
        s[r] = v.x * v.x + v.y * v.y + v.z * v.z + v.w * v.w;
    }
#pragma unroll
    for (int o = 16; o; o >>= 1)
#pragma unroll
        for (int r = 0; r < 8; r++) s[r] += __shfl_xor_sync(0xffffffffu, s[r], o);
    if (lane == 0) {
        float mx = s[0];
#pragma unroll
        for (int r = 1; r < 8; r++) mx = fmaxf(mx, s[r]);
        atomicMax(&g_cm2[level][(w * 8) >> 11], __float_as_uint(mx));
    }
}

__device__ __forceinline__ float warp_sum(float v) {
#pragma unroll
    for (int o = 16; o; o >>= 1) v += __shfl_xor_sync(0xffffffffu, v, o);
    return v;
}
__device__ __forceinline__ float warp_max_pos(float v) {   // non-negative floats
    unsigned r;
    asm("redux.sync.max.u32 %0, %1, 0xffffffff;" : "=r"(r) : "r"(__float_as_uint(v)));
    return __uint_as_float(r);
}

__constant__ float c_SCALE = 45.25483399593904f;   // sqrt(2048)

// Exact threshold: g(u) = -log(-log u) monotone; candidate iff u >= uthr.
// delta = Cauchy-Schwarz logit-spread bound, inflated for fp noise.
__device__ __forceinline__ float make_uthr(float umax, float t, float x2, float cm2) {
    const float EPSF = 1e-6f, HI = (float)(1.0 - 1e-6);
    const float cmax = sqrtf(cm2);
    float delta = (t / c_SCALE) * (4.0f * sqrtf(x2) * cmax + cm2);
    delta = delta * 1.01f + 0.02f;
    float ucm  = fminf(fmaxf(umax, EPSF), HI);
    float gm   = -logf(-logf(ucm));
    float uthr = expf(-expf(-(gm - delta))) * (1.0f - 1e-5f);
    return fminf(uthr, umax);                 // max element always qualifies
}

// ---- K1: pure streaming. One warp per (row, level): burst, redux max,
// branch-free mask vs fixed UTHR0, push speculative candidates. Tiny tail.
__global__ void __launch_bounds__(256) stream_k(
    const float* __restrict__ u0, const float* __restrict__ u1)
{
    __shared__ int   s_cnt[8];
    __shared__ int   s_k[8][CAPG];
    __shared__ float s_u[8][CAPG];
    const int w    = threadIdx.x >> 5;
    const int lane = threadIdx.x & 31;
    const int row  = blockIdx.x * 8 + w;
    const int lvl  = blockIdx.y;
    const float4* urow = reinterpret_cast<const float4*>(lvl ? u1 : u0)
                         + (size_t)row * (KQ / 4);

    // Front-batched burst: load + fmax ONLY.
    float4 ur[16];
    float umax = 0.0f;
#pragma unroll
    for (int j = 0; j < 16; j++) {
        ur[j] = urow[j * 32 + lane];
        umax = fmaxf(umax, fmaxf(fmaxf(ur[j].x, ur[j].y), fmaxf(ur[j].z, ur[j].w)));
    }
    if (lane == 0) s_cnt[w] = 0;
    umax = warp_max_pos(umax);

    // Branch-free mask vs fixed threshold; one ballot; divergent pushes.
    unsigned m0 = 0u, m1 = 0u;
#pragma unroll
    for (int j = 0; j < 16; j++) {
        const float4 v = ur[j];
        unsigned b = (unsigned)(v.x >= UTHR0) | ((unsigned)(v.y >= UTHR0) << 1)
                   | ((unsigned)(v.z >= UTHR0) << 2) | ((unsigned)(v.w >= UTHR0) << 3);
        if (j < 8) m0 |= b << (4 * j); else m1 |= b << (4 * (j - 8));
    }
    __syncwarp();
    __ballot_sync(0xffffffffu, (m0 | m1) != 0u);
    if (m0 | m1) {
#pragma unroll
        for (int j = 0; j < 16; j++) {
            unsigned b = (j < 8) ? (m0 >> (4 * j)) & 0xFu : (m1 >> (4 * (j - 8))) & 0xFu;
            if (b) {
                const int kb = (j * 32 + lane) * 4;
                const float4 v = ur[j];
                if (b & 1u) { int q = atomicAdd(&s_cnt[w], 1); if (q < CAPG) { s_k[w][q] = kb + 0; s_u[w][q] = v.x; } }
                if (b & 2u) { int q = atomicAdd(&s_cnt[w], 1); if (q < CAPG) { s_k[w][q] = kb + 1; s_u[w][q] = v.y; } }
                if (b & 4u) { int q = atomicAdd(&s_cnt[w], 1); if (q < CAPG) { s_k[w][q] = kb + 2; s_u[w][q] = v.z; } }
                if (b & 8u) { int q = atomicAdd(&s_cnt[w], 1); if (q < CAPG) { s_k[w][q] = kb + 3; s_u[w][q] = v.w; } }
            }
        }
    }
    __syncwarp();
    const int cnt = s_cnt[w];
    if (lane == 0) { g_cap[lvl][row] = cnt; g_umax[lvl][row] = umax; }
    for (int i = lane; i < cnt && i < CAPG; i += 32)
        g_cand[lvl][row][i] = make_uint2(__float_as_uint(s_u[w][i]), (unsigned)s_k[w][i]);
}

// Candidate list for one level: filter speculative list by exact uthr (common),
// or re-stream the u row (rare ~5e-4). Result set = {k : u_k >= uthr} exactly.
__device__ __forceinline__ int gather_cands(
    int lvl, int row, float uthr, const float* __restrict__ u,
    int lane, int* s_cnt, int* kl, float* ul)
{
    if (lane == 0) *s_cnt = 0;
    __syncwarp();
    const int cntraw = g_cap[lvl][row];
    if (uthr >= UTHR0 && cntraw <= CAPG) {
        for (int i = lane; i < cntraw; i += 32) {
            uint2 e = g_cand[lvl][row][i];
            float uv = __uint_as_float(e.x);
            if (uv >= uthr) { int q = atomicAdd(s_cnt, 1); kl[q] = (int)e.y; ul[q] = uv; }
        }
    } else {
        const float4* urow = reinterpret_cast<const float4*>(u) + (size_t)row * (KQ / 4);
#pragma unroll 1
        for (int j = 0; j < 16; j++) {
            const float4 v = urow[j * 32 + lane];
            if (fmaxf(fmaxf(v.x, v.y), fmaxf(v.z, v.w)) >= uthr) {
                const int kb = (j * 32 + lane) * 4;
                if (v.x >= uthr) { int q = atomicAdd(s_cnt, 1); if (q < CAP) { kl[q] = kb + 0; ul[q] = v.x; } }
                if (v.y >= uthr) { int q = atomicAdd(s_cnt, 1); if (q < CAP) { kl[q] = kb + 1; ul[q] = v.y; } }
                if (v.z >= uthr) { int q = atomicAdd(s_cnt, 1); if (q < CAP) { kl[q] = kb + 2; ul[q] = v.z; } }
                if (v.w >= uthr) { int q = atomicAdd(s_cnt, 1); if (q < CAP) { kl[q] = kb + 3; ul[q] = v.w; } }
            }
        }
    }
    __syncwarp();
    int cnt = *s_cnt;
    return cnt > CAP ? CAP : cnt;
}

// Score candidates; returns best k and leaves its codebook row (this lane's 4
// dims) in *bc — avoids a dependent re-gather on the common path.
__device__ __forceinline__ int score_pick(
    float4 z, float x2, float t, const float* __restrict__ cbm,
    int cnt, const int* kl, const float* ul, int lane, float4* bc)
{
    const float EPSF = 1e-6f, HI = (float)(1.0 - 1e-6);
    float best_s = -3.4e38f, sec_s = -3.4e38f;
    int   best_k = 0;
    for (int base = 0; base < cnt; base += 2) {
        float dd[2]; int kk[2]; float4 cc[2];
#pragma unroll
        for (int i2 = 0; i2 < 2; i2++) {
            int i = base + i2; if (i > cnt - 1) i = cnt - 1;
            int k = kl[i]; kk[i2] = k;
            float4 c = reinterpret_cast<const float4*>(cbm)[(size_t)k * (DQ / 4) + lane];
            cc[i2] = c;
            float ex = z.x - c.x, ey = z.y - c.y, ez = z.z - c.z, ew = z.w - c.w;
            dd[i2] = ex * ex + ey * ey + ez * ez + ew * ew;
        }
#pragma unroll
        for (int o = 16; o; o >>= 1) {
            dd[0] += __shfl_xor_sync(0xffffffffu, dd[0], o);
            dd[1] += __shfl_xor_sync(0xffffffffu, dd[1], o);
        }
#pragma unroll
        for (int i2 = 0; i2 < 2; i2++) {
            int i = base + i2; if (i >= cnt) break;
            float uc = fminf(fmaxf(ul[i], EPSF), HI);
            float g  = -logf(-logf(uc));
            float sc = -dd[i2] / c_SCALE * t + g;
            int   k  = kk[i2];
            if (sc > best_s || (sc == best_s && k < best_k)) {
                sec_s = best_s; best_s = sc; best_k = k; *bc = cc[i2];
            } else if (sc > sec_s) sec_s = sc;
        }
    }

    if (cnt >= 2 && best_s - sec_s < 1e-2f) {   // rare: reference-faithful rescore
        best_s = -3.4e38f; best_k = 0;
        for (int i = 0; i < cnt; i++) {
            const int k = kl[i];
            float4 c = reinterpret_cast<const float4*>(cbm)[(size_t)k * (DQ / 4) + lane];
            float p = warp_sum(z.x * c.x + z.y * c.y + z.z * c.z + z.w * c.w);
            float q = warp_sum(c.x * c.x + c.y * c.y + c.z * c.z + c.w * c.w);
            double ucl = (double)fminf(fmaxf(ul[i], EPSF), HI);
            float  g   = (float)(-log(-log(ucl)));
            float dist  = __fadd_rn(__fadd_rn(x2, q), -__fmul_rn(2.0f, p));
            float logit = __fmul_rn(__fdiv_rn(-dist, c_SCALE), t);
            float sc    = __fadd_rn(logit, g);
            if (sc > best_s || (sc == best_s && k < best_k)) { best_s = sc; best_k = k; }
        }
        *bc = reinterpret_cast<const float4*>(cbm)[(size_t)best_k * (DQ / 4) + lane];
    }
    __syncwarp();
    return best_k;
}

// ---- K2: fused scoring for BOTH levels + output. No ur[16] -> low regs. ----
__global__ void __launch_bounds__(256) score_k(
    const float* __restrict__ x,
    const float* __restrict__ cb0, const float* __restrict__ cb1,
    const float* __restrict__ t0p, const float* __restrict__ t1p,
    const float* __restrict__ u0,  const float* __restrict__ u1,
    float* __restrict__ out)
{
    __shared__ int   s_cnt[8];
    __shared__ int   s_k[8][CAP];
    __shared__ float s_u[8][CAP];
    const int w    = threadIdx.x >> 5;
    const int lane = threadIdx.x & 31;
    const int row  = blockIdx.x * 8 + w;
    const int n    = row >> 3;
    const int m    = row & 7;

    // Front-load independent row scalars (overlap their latencies).
    float4 z   = reinterpret_cast<const float4*>(x + (size_t)n * CH + m * DQ)[lane];
    const float um0 = g_umax[0][row];
    const float um1 = g_umax[1][row];
    const float t0  = fmaxf(t0p[m], 1e-6f);
    const float t1  = fmaxf(t1p[m], 1e-6f);
    const float cm20 = __uint_as_float(g_cm2[0][m]);
    const float cm21 = __uint_as_float(g_cm2[1][m]);
    const float* cbm0 = cb0 + (size_t)m * KQ * DQ;
    const float* cbm1 = cb1 + (size_t)m * KQ * DQ;

    float x2 = warp_sum(z.x * z.x + z.y * z.y + z.z * z.z + z.w * z.w);

    // ---- level 0 ----
    float uthr0 = make_uthr(um0, t0, x2, cm20);
    int cnt0 = gather_cands(0, row, uthr0, u0, lane, &s_cnt[w], s_k[w], s_u[w]);
    float4 c0;
    score_pick(z, x2, t0, cbm0, cnt0, s_k[w], s_u[w], lane, &c0);

    float4 z1 = make_float4(z.x - c0.x, z.y - c0.y, z.z - c0.z, z.w - c0.w);
    float x2b = warp_sum(z1.x * z1.x + z1.y * z1.y + z1.z * z1.z + z1.w * z1.w);

    // ---- level 1 ----
    float uthr1 = make_uthr(um1, t1, x2b, cm21);
    int cnt1 = gather_cands(1, row, uthr1, u1, lane, &s_cnt[w], s_k[w], s_u[w]);
    float4 c1;
    score_pick(z1, x2b, t1, cbm1, cnt1, s_k[w], s_u[w], lane, &c1);

    float4 o = make_float4(c0.x + c1.x, c0.y + c1.y, c0.z + c1.z, c0.w + c1.w);
    reinterpret_cast<float4*>(out + (size_t)n * CH + m * DQ)[lane] = o;
}

extern "C" void kernel_launch(void* const* d_in, const int* in_sizes, int n_in,
                              void* d_out, int out_size) {
    const float *x = nullptr, *cb0 = nullptr, *cb1 = nullptr,
                *t0 = nullptr, *t1 = nullptr, *u0 = nullptr, *u1 = nullptr;
    for (int i = 0; i < n_in; i++) {
        const float* p = (const float*)d_in[i];
        const long sz = in_sizes[i];
        if      (sz == (long)NROW * CH)        { x = p; }
        else if (sz == (long)MQ * KQ * DQ)     { if (!cb0) cb0 = p; else cb1 = p; }
        else if (sz == (long)MQ)               { if (!t0)  t0  = p; else t1  = p; }
        else if (sz == (long)NROW * MQ * KQ)   { if (!u0)  u0  = p; else u1  = p; }
    }
    float* out = (float*)d_out;
    (void)out_size;

    dim3 gc((MQ * KQ) / (8 * 8), 2);             // 8 k's/warp, 8 warps/block
    cm2_k<<<gc, 256>>>(cb0, cb1);
    dim3 gs((NROW * MQ) / 8, 2);                 // one warp per (row, level)
    stream_k<<<gs, 256>>>(u0, u1);
    score_k<<<(NROW * MQ) / 8, 256>>>(x, cb0, cb1, t0, t1, u0, u1, out);
}

// round 13
// speedup vs baseline: 1.2278x; 1.1742x over previous
#include <cuda_runtime.h>
#include <math.h>
#include <stdint.h>

#define NROW 4096
#define CH   1024
#define MQ   8
#define KQ   2048
#define DQ   128
#define CAP  64

// Per-(level,m) max_k |c_k|^2, as ordered uint (floats >= 0). Zero-initialized at
// module load; atomicMax over a fixed input set is idempotent across graph replays.
static __device__ unsigned g_cm2[2][MQ];

// One warp per 8 consecutive k: 8 interleaved butterflies, one atomicMax.
__global__ void cm2_k(const float* __restrict__ cb0, const float* __restrict__ cb1) {
    const int level = blockIdx.y;
    const float* cb = level ? cb1 : cb0;
    const int w    = (blockIdx.x * blockDim.x + threadIdx.x) >> 5;
    const int lane = threadIdx.x & 31;
    if (w >= (MQ * KQ) / 8) return;
    float s[8];
#pragma unroll
    for (int r = 0; r < 8; r++) {
        float4 v = reinterpret_cast<const float4*>(cb)[(size_t)(w * 8 + r) * (DQ / 4) + lane];
        s[r] = v.x * v.x + v.y * v.y + v.z * v.z + v.w * v.w;
    }
#pragma unroll
    for (int o = 16; o; o >>= 1)
#pragma unroll
        for (int r = 0; r < 8; r++) s[r] += __shfl_xor_sync(0xffffffffu, s[r], o);
    if (lane == 0) {
        float mx = s[0];
#pragma unroll
        for (int r = 1; r < 8; r++) mx = fmaxf(mx, s[r]);
        atomicMax(&g_cm2[level][(w * 8) >> 11], __float_as_uint(mx));
    }
}

__device__ __forceinline__ float warp_sum(float v) {
#pragma unroll
    for (int o = 16; o; o >>= 1) v += __shfl_xor_sync(0xffffffffu, v, o);
    return v;
}
__device__ __forceinline__ float warp_max_pos(float v) {   // non-negative floats
    unsigned r;
    asm("redux.sync.max.u32 %0, %1, 0xffffffff;" : "=r"(r) : "r"(__float_as_uint(v)));
    return __uint_as_float(r);
}

// One warp, one (n,m) row, one level: u row cached fully in registers (MLP=16),
// gumbel-max pruning (single-ballot pass 2), single-butterfly fp32 scoring,
// fp64-faithful refinement on near-ties.
__device__ __forceinline__ int pick_code(
    float4 z, float x2, float t,
    const float* __restrict__ cbm,
    float cm2,
    const float4* __restrict__ u4row,
    int lane, int* s_cnt, int* s_kl, float* s_ul)
{
    if (lane == 0) *s_cnt = 0;

    // Pass 1: one front-batched burst of 16 LDG.128/lane + running max.
    float4 ur[16];
    float umax = 0.0f;
#pragma unroll
    for (int j = 0; j < 16; j++) {
        ur[j] = u4row[j * 32 + lane];
        umax = fmaxf(umax, fmaxf(fmaxf(ur[j].x, ur[j].y), fmaxf(ur[j].z, ur[j].w)));
    }
    umax = warp_max_pos(umax);

    const float SCALE = 45.25483399593904f;   // sqrt(2048)
    const float EPSF  = 1e-6f;
    const float HI    = (float)(1.0 - 1e-6);

    // Rigorous spread bound of logit over k (Cauchy-Schwarz), inflated for fp noise.
    const float cmax = sqrtf(cm2);
    float delta = (t / SCALE) * (4.0f * sqrtf(x2) * cmax + cm2);
    delta = delta * 1.01f + 0.02f;

    // g(u) = -log(-log u) monotone in u: candidate iff u >= uthr.
    float ucm  = fminf(fmaxf(umax, EPSF), HI);
    float gm   = -logf(-logf(ucm));
    float uthr = expf(-expf(-(gm - delta))) * (1.0f - 1e-5f);
    uthr = fminf(uthr, umax);     // guarantees the max element qualifies

    // Pass 2: branch-free per-lane 64-bit candidate mask, ONE ballot, then
    // divergent pushes on the rare lanes that own candidates.
    unsigned m0 = 0u, m1 = 0u;
#pragma unroll
    for (int j = 0; j < 16; j++) {
        const float4 v = ur[j];
        unsigned b = (unsigned)(v.x >= uthr) | ((unsigned)(v.y >= uthr) << 1)
                   | ((unsigned)(v.z >= uthr) << 2) | ((unsigned)(v.w >= uthr) << 3);
        if (j < 8) m0 |= b << (4 * j); else m1 |= b << (4 * (j - 8));
    }
    __syncwarp();                                  // s_cnt reset visible
    __ballot_sync(0xffffffffu, (m0 | m1) != 0u);   // reconverge; >=1 lane set
    if (m0 | m1) {
#pragma unroll
        for (int j = 0; j < 16; j++) {
            unsigned b = (j < 8) ? (m0 >> (4 * j)) & 0xFu : (m1 >> (4 * (j - 8))) & 0xFu;
            if (b) {
                const int kb = (j * 32 + lane) * 4;
                const float4 v = ur[j];
                if (b & 1u) { int q = atomicAdd(s_cnt, 1); if (q < CAP) { s_kl[q] = kb + 0; s_ul[q] = v.x; } }
                if (b & 2u) { int q = atomicAdd(s_cnt, 1); if (q < CAP) { s_kl[q] = kb + 1; s_ul[q] = v.y; } }
                if (b & 4u) { int q = atomicAdd(s_cnt, 1); if (q < CAP) { s_kl[q] = kb + 2; s_ul[q] = v.z; } }
                if (b & 8u) { int q = atomicAdd(s_cnt, 1); if (q < CAP) { s_kl[q] = kb + 3; s_ul[q] = v.w; } }
            }
        }
    }
    __syncwarp();
    int cnt = *s_cnt;
    if (cnt > CAP) cnt = CAP;              // statistically unreachable
    if (cnt <= 1) return s_kl[0];          // umax always qualifies -> cnt >= 1

    // Fast scoring: dist = sum_d (z_d - c_d)^2 -> ONE butterfly per candidate,
    // 2-wide ILP. Reassociation noise vs the faithful formula is covered by the
    // 1e-2 refinement margin below.
    float best_s = -3.4e38f, sec_s = -3.4e38f;
    int   best_k = 0;
    for (int base = 0; base < cnt; base += 2) {
        float dd[2]; int kk[2];
#pragma unroll
        for (int i2 = 0; i2 < 2; i2++) {
            int i = base + i2; if (i > cnt - 1) i = cnt - 1;
            int k = s_kl[i]; kk[i2] = k;
            float4 c = reinterpret_cast<const float4*>(cbm)[(size_t)k * (DQ / 4) + lane];
            float ex = z.x - c.x, ey = z.y - c.y, ez = z.z - c.z, ew = z.w - c.w;
            dd[i2] = ex * ex + ey * ey + ez * ez + ew * ew;
        }
#pragma unroll
        for (int o = 16; o; o >>= 1) {
            dd[0] += __shfl_xor_sync(0xffffffffu, dd[0], o);
            dd[1] += __shfl_xor_sync(0xffffffffu, dd[1], o);
        }
#pragma unroll
        for (int i2 = 0; i2 < 2; i2++) {
            int i = base + i2; if (i >= cnt) break;
            float uc = fminf(fmaxf(s_ul[i], EPSF), HI);
            float g  = -logf(-logf(uc));
            float sc = -dd[i2] / SCALE * t + g;
            int   k  = kk[i2];
            if (sc > best_s || (sc == best_s && k < best_k)) {
                sec_s = best_s; best_s = sc; best_k = k;
            } else if (sc > sec_s) sec_s = sc;
        }
    }

    // Refinement (rare, ~1e-2 of rows): reference-faithful fp32 formula with
    // fp64 gumbel. Margin 1e-2 >> combined fp noise of both paths (<~3e-4).
    if (best_s - sec_s < 1e-2f) {
        best_s = -3.4e38f; best_k = 0;
        for (int i = 0; i < cnt; i++) {
            const int k = s_kl[i];
            float4 c = reinterpret_cast<const float4*>(cbm)[(size_t)k * (DQ / 4) + lane];
            float p = warp_sum(z.x * c.x + z.y * c.y + z.z * c.z + z.w * c.w);
            float q = warp_sum(c.x * c.x + c.y * c.y + c.z * c.z + c.w * c.w);
            double ucl = (double)fminf(fmaxf(s_ul[i], EPSF), HI);
            float  g   = (float)(-log(-log(ucl)));
            float dist  = __fadd_rn(__fadd_rn(x2, q), -__fmul_rn(2.0f, p));
            float logit = __fmul_rn(__fdiv_rn(-dist, SCALE), t);
            float sc    = __fadd_rn(logit, g);
            if (sc > best_s || (sc == best_s && k < best_k)) { best_s = sc; best_k = k; }
        }
    }
    __syncwarp();
    return best_k;
}

__global__ void __launch_bounds__(256) umgm_kernel(
    const float* __restrict__ x,
    const float* __restrict__ cb0,
    const float* __restrict__ cb1,
    const float* __restrict__ t0p,
    const float* __restrict__ t1p,
    const float* __restrict__ u0,
    const float* __restrict__ u1,
    float* __restrict__ out)
{
    __shared__ int   s_cnt[8];
    __shared__ int   s_k[8][CAP];
    __shared__ float s_u[8][CAP];
    const int w    = threadIdx.x >> 5;
    const int lane = threadIdx.x & 31;
    const int row  = blockIdx.x * 8 + w;   // row = n*M + m (matches u layout)
    const int n    = row >> 3;
    const int m    = row & 7;
    const float EPSF = 1e-6f;

    float4 z = reinterpret_cast<const float4*>(x + (size_t)n * CH + m * DQ)[lane];
    float x2 = warp_sum(z.x * z.x + z.y * z.y + z.z * z.z + z.w * z.w);

    const float* cbm0 = cb0 + (size_t)m * KQ * DQ;
    const float* cbm1 = cb1 + (size_t)m * KQ * DQ;

    // ---- level 0 ----
    int k0 = pick_code(z, x2, fmaxf(t0p[m], EPSF), cbm0,
                       __uint_as_float(g_cm2[0][m]),
                       reinterpret_cast<const float4*>(u0) + (size_t)row * (KQ / 4),
                       lane, &s_cnt[w], s_k[w], s_u[w]);
    float4 c0 = reinterpret_cast<const float4*>(cbm0)[(size_t)k0 * (DQ / 4) + lane];

    float4 z1 = make_float4(z.x - c0.x, z.y - c0.y, z.z - c0.z, z.w - c0.w);
    float x2b = warp_sum(z1.x * z1.x + z1.y * z1.y + z1.z * z1.z + z1.w * z1.w);

    // ---- level 1 ----
    int k1 = pick_code(z1, x2b, fmaxf(t1p[m], EPSF), cbm1,
                       __uint_as_float(g_cm2[1][m]),
                       reinterpret_cast<const float4*>(u1) + (size_t)row * (KQ / 4),
                       lane, &s_cnt[w], s_k[w], s_u[w]);
    float4 c1 = reinterpret_cast<const float4*>(cbm1)[(size_t)k1 * (DQ / 4) + lane];

    float4 o = make_float4(c0.x + c1.x, c0.y + c1.y, c0.z + c1.z, c0.w + c1.w);
    reinterpret_cast<float4*>(out + (size_t)n * CH + m * DQ)[lane] = o;
}

extern "C" void kernel_launch(void* const* d_in, const int* in_sizes, int n_in,
                              void* d_out, int out_size) {
    const float *x = nullptr, *cb0 = nullptr, *cb1 = nullptr,
                *t0 = nullptr, *t1 = nullptr, *u0 = nullptr, *u1 = nullptr;
    for (int i = 0; i < n_in; i++) {
        const float* p = (const float*)d_in[i];
        const long sz = in_sizes[i];
        if      (sz == (long)NROW * CH)        { x = p; }
        else if (sz == (long)MQ * KQ * DQ)     { if (!cb0) cb0 = p; else cb1 = p; }
        else if (sz == (long)MQ)               { if (!t0)  t0  = p; else t1  = p; }
        else if (sz == (long)NROW * MQ * KQ)   { if (!u0)  u0  = p; else u1  = p; }
    }
    float* out = (float*)d_out;
    (void)out_size;

    dim3 gc((MQ * KQ) / (8 * 8), 2);       // 8 k's per warp, 8 warps/block
    cm2_k<<<gc, 256>>>(cb0, cb1);
    umgm_kernel<<<(NROW * MQ) / 8, 256>>>(x, cb0, cb1, t0, t1, u0, u1, out);
}

// round 14
// speedup vs baseline: 1.5890x; 1.2942x over previous
#include <cuda_runtime.h>
#include <math.h>
#include <stdint.h>

#define NROW 4096
#define CH   1024
#define MQ   8
#define KQ   2048
#define DQ   128
#define CAP  64

// Per-(level,m) max_k |c_k|^2, as ordered uint (floats >= 0). Zero-initialized at
// module load; atomicMax over a fixed input set is idempotent across graph replays.
static __device__ unsigned g_cm2[2][MQ];

// One warp per 8 consecutive k: 8 interleaved butterflies (MLP=8), one atomicMax.
// (Measured 8.16us in R12 vs ~20us for the 1-k/warp version.)
__global__ void cm2_k(const float* __restrict__ cb0, const float* __restrict__ cb1) {
    const int level = blockIdx.y;
    const float* cb = level ? cb1 : cb0;
    const int w    = (blockIdx.x * blockDim.x + threadIdx.x) >> 5;
    const int lane = threadIdx.x & 31;
    if (w >= (MQ * KQ) / 8) return;
    float s[8];
#pragma unroll
    for (int r = 0; r < 8; r++) {
        float4 v = reinterpret_cast<const float4*>(cb)[(size_t)(w * 8 + r) * (DQ / 4) + lane];
        s[r] = v.x * v.x + v.y * v.y + v.z * v.z + v.w * v.w;
    }
#pragma unroll
    for (int o = 16; o; o >>= 1)
#pragma unroll
        for (int r = 0; r < 8; r++) s[r] += __shfl_xor_sync(0xffffffffu, s[r], o);
    if (lane == 0) {
        float mx = s[0];
#pragma unroll
        for (int r = 1; r < 8; r++) mx = fmaxf(mx, s[r]);
        atomicMax(&g_cm2[level][(w * 8) >> 11], __float_as_uint(mx));
    }
}

__device__ __forceinline__ float warp_sum(float v) {
#pragma unroll
    for (int o = 16; o; o >>= 1) v += __shfl_xor_sync(0xffffffffu, v, o);
    return v;
}
__device__ __forceinline__ float warp_max(float v) {
#pragma unroll
    for (int o = 16; o; o >>= 1) v = fmaxf(v, __shfl_xor_sync(0xffffffffu, v, o));
    return v;
}

// One warp, one (n,m) row, one level: scan u (2048 floats, kept in regs),
// gumbel-max pruning, fp32 scoring of the few candidates, fp64 re-score only
// on near-ties. (Byte-for-byte the R2 source — measured 151.5us.)
__device__ __forceinline__ int pick_code(
    float4 z, float x2, float t,
    const float* __restrict__ cbm,   // codebook + m*K*D
    float cm2,
    const float4* __restrict__ u4row,
    int lane, int* s_cnt, int* s_kl, float* s_ul)
{
    if (lane == 0) *s_cnt = 0;

    // Pass 1: stream u row into registers (16 LDG.128/lane, front-batched) + running max.
    float4 ur[16];
    float umax = 0.0f;
#pragma unroll
    for (int j = 0; j < 16; j++) {
        ur[j] = u4row[j * 32 + lane];
        umax = fmaxf(umax, fmaxf(fmaxf(ur[j].x, ur[j].y), fmaxf(ur[j].z, ur[j].w)));
    }
    umax = warp_max(umax);

    const float SCALE = 45.25483399593904f;   // sqrt(2048)
    const float EPSF  = 1e-6f;
    const float HI    = (float)(1.0 - 1e-6);

    // Rigorous spread bound of logit over k (Cauchy-Schwarz), inflated for fp noise.
    const float cmax = sqrtf(cm2);
    float delta = (t / SCALE) * (4.0f * sqrtf(x2) * cmax + cm2);
    delta = delta * 1.01f + 0.02f;

    // g(u) = -log(-log u) is monotone in u: candidate iff u >= uthr.
    float ucm  = fminf(fmaxf(umax, EPSF), HI);
    float gm   = -logf(-logf(ucm));
    float uthr = expf(-expf(-(gm - delta))) * (1.0f - 1e-5f);
    uthr = fminf(uthr, umax);

    __syncwarp();
    // Pass 2: slab-level warp-uniform skip via ballot; rare pushes to smem list.
#pragma unroll
    for (int j = 0; j < 16; j++) {
        const float4 v = ur[j];
        unsigned p = (unsigned)(v.x >= uthr) | ((unsigned)(v.y >= uthr) << 1)
                   | ((unsigned)(v.z >= uthr) << 2) | ((unsigned)(v.w >= uthr) << 3);
        if (__ballot_sync(0xffffffffu, p != 0u)) {
            const int kb = (j * 32 + lane) * 4;
            if (p & 1u) { int q = atomicAdd(s_cnt, 1); if (q < CAP) { s_kl[q] = kb + 0; s_ul[q] = v.x; } }
            if (p & 2u) { int q = atomicAdd(s_cnt, 1); if (q < CAP) { s_kl[q] = kb + 1; s_ul[q] = v.y; } }
            if (p & 4u) { int q = atomicAdd(s_cnt, 1); if (q < CAP) { s_kl[q] = kb + 2; s_ul[q] = v.z; } }
            if (p & 8u) { int q = atomicAdd(s_cnt, 1); if (q < CAP) { s_kl[q] = kb + 3; s_ul[q] = v.w; } }
        }
    }
    __syncwarp();
    int cnt = *s_cnt;
    if (cnt > CAP) cnt = CAP;              // statistically unreachable
    if (cnt <= 1) return s_kl[0];          // max element always passes -> cnt >= 1

    // Fast scoring: 4-wide ILP batches, fp32 gumbel (MUFU). Track top-2 gap.
    float best_s = -3.4e38f, sec_s = -3.4e38f;
    int   best_k = 0;
    for (int base = 0; base < cnt; base += 4) {
        float pq[4], qq[4]; int kk[4];
#pragma unroll
        for (int i4 = 0; i4 < 4; i4++) {
            int i = base + i4; if (i > cnt - 1) i = cnt - 1;
            int k = s_kl[i]; kk[i4] = k;
            float4 c = reinterpret_cast<const float4*>(cbm)[(size_t)k * (DQ / 4) + lane];
            pq[i4] = z.x * c.x + z.y * c.y + z.z * c.z + z.w * c.w;
            qq[i4] = c.x * c.x + c.y * c.y + c.z * c.z + c.w * c.w;
        }
#pragma unroll
        for (int o = 16; o; o >>= 1) {                 // interleaved butterflies (ILP)
#pragma unroll
            for (int i4 = 0; i4 < 4; i4++) {
                pq[i4] += __shfl_xor_sync(0xffffffffu, pq[i4], o);
                qq[i4] += __shfl_xor_sync(0xffffffffu, qq[i4], o);
            }
        }
#pragma unroll
        for (int i4 = 0; i4 < 4; i4++) {
            int i = base + i4; if (i >= cnt) break;
            float uc = fminf(fmaxf(s_ul[i], EPSF), HI);
            float g  = -logf(-logf(uc));
            float dist  = __fadd_rn(__fadd_rn(x2, qq[i4]), -__fmul_rn(2.0f, pq[i4]));
            float logit = __fmul_rn(__fdiv_rn(-dist, SCALE), t);
            float sc    = __fadd_rn(logit, g);
            int   k     = kk[i4];
            if (sc > best_s || (sc == best_s && k < best_k)) {
                sec_s = best_s; best_s = sc; best_k = k;
            } else if (sc > sec_s) sec_s = sc;
        }
    }

    // Refinement (rare, ~1e-3 of rows): exact fp64-gumbel rescore, identical to the
    // reference-faithful formula. Margin 3e-3 >> fp32/fast-math log error (<=1e-5).
    if (best_s - sec_s < 3e-3f) {
        best_s = -3.4e38f; best_k = 0;
        for (int i = 0; i < cnt; i++) {
            const int k = s_kl[i];
            float4 c = reinterpret_cast<const float4*>(cbm)[(size_t)k * (DQ / 4) + lane];
            float p = warp_sum(z.x * c.x + z.y * c.y + z.z * c.z + z.w * c.w);
            float q = warp_sum(c.x * c.x + c.y * c.y + c.z * c.z + c.w * c.w);
            double ucl = (double)fminf(fmaxf(s_ul[i], EPSF), HI);
            float  g   = (float)(-log(-log(ucl)));
            float dist  = __fadd_rn(__fadd_rn(x2, q), -__fmul_rn(2.0f, p));
            float logit = __fmul_rn(__fdiv_rn(-dist, SCALE), t);
            float sc    = __fadd_rn(logit, g);
            if (sc > best_s || (sc == best_s && k < best_k)) { best_s = sc; best_k = k; }
        }
    }
    __syncwarp();
    return best_k;
}

__global__ void __launch_bounds__(256) umgm_kernel(
    const float* __restrict__ x,
    const float* __restrict__ cb0,
    const float* __restrict__ cb1,
    const float* __restrict__ t0p,
    const float* __restrict__ t1p,
    const float* __restrict__ u0,
    const float* __restrict__ u1,
    float* __restrict__ out)
{
    __shared__ int   s_cnt[8];
    __shared__ int   s_k[8][CAP];
    __shared__ float s_u[8][CAP];
    const int w    = threadIdx.x >> 5;
    const int lane = threadIdx.x & 31;
    const int row  = blockIdx.x * 8 + w;   // row = n*M + m (matches u layout)
    const int n    = row >> 3;
    const int m    = row & 7;
    const float EPSF = 1e-6f;

    // z row (dims [4*lane, 4*lane+4)) and |z|^2
    float4 z = reinterpret_cast<const float4*>(x + (size_t)n * CH + m * DQ)[lane];
    float x2 = warp_sum(z.x * z.x + z.y * z.y + z.z * z.z + z.w * z.w);

    const float* cbm0 = cb0 + (size_t)m * KQ * DQ;
    const float* cbm1 = cb1 + (size_t)m * KQ * DQ;

    // ---- level 0 ----
    int k0 = pick_code(z, x2, fmaxf(t0p[m], EPSF), cbm0,
                       __uint_as_float(g_cm2[0][m]),
                       reinterpret_cast<const float4*>(u0) + (size_t)row * (KQ / 4),
                       lane, &s_cnt[w], s_k[w], s_u[w]);
    float4 c0 = reinterpret_cast<const float4*>(cbm0)[(size_t)k0 * (DQ / 4) + lane];

    // residual x1 = x - deq0 (bitwise same op as reference)
    float4 z1 = make_float4(z.x - c0.x, z.y - c0.y, z.z - c0.z, z.w - c0.w);
    float x2b = warp_sum(z1.x * z1.x + z1.y * z1.y + z1.z * z1.z + z1.w * z1.w);

    // ---- level 1 ----
    int k1 = pick_code(z1, x2b, fmaxf(t1p[m], EPSF), cbm1,
                       __uint_as_float(g_cm2[1][m]),
                       reinterpret_cast<const float4*>(u1) + (size_t)row * (KQ / 4),
                       lane, &s_cnt[w], s_k[w], s_u[w]);
    float4 c1 = reinterpret_cast<const float4*>(cbm1)[(size_t)k1 * (DQ / 4) + lane];

    // xHat = deq0 + deq1
    float4 o = make_float4(c0.x + c1.x, c0.y + c1.y, c0.z + c1.z, c0.w + c1.w);
    reinterpret_cast<float4*>(out + (size_t)n * CH + m * DQ)[lane] = o;
}

extern "C" void kernel_launch(void* const* d_in, const int* in_sizes, int n_in,
                              void* d_out, int out_size) {
    const float *x = nullptr, *cb0 = nullptr, *cb1 = nullptr,
                *t0 = nullptr, *t1 = nullptr, *u0 = nullptr, *u1 = nullptr;
    for (int i = 0; i < n_in; i++) {
        const float* p = (const float*)d_in[i];
        const long sz = in_sizes[i];
        if      (sz == (long)NROW * CH)        { x = p; }
        else if (sz == (long)MQ * KQ * DQ)     { if (!cb0) cb0 = p; else cb1 = p; }
        else if (sz == (long)MQ)               { if (!t0)  t0  = p; else t1  = p; }
        else if (sz == (long)NROW * MQ * KQ)   { if (!u0)  u0  = p; else u1  = p; }
    }
    float* out = (float*)d_out;
    (void)out_size;

    dim3 gc((MQ * KQ) / (8 * 8), 2);       // 8 k's per warp, 8 warps/block
    cm2_k<<<gc, 256>>>(cb0, cb1);
    umgm_kernel<<<(NROW * MQ) / 8, 256>>>(x, cb0, cb1, t0, t1, u0, u1, out);
}